// round 12
// baseline (speedup 1.0000x reference)
#include <cuda_runtime.h>

#define DIM    100
#define NW     39
#define NH     4
#define NSLICE 4800
#define NTHR   256          // 8 warps, 1 slice per warp
#define NBLK   (NSLICE / 8) // 600
#define SEPITCH 160         // floats per warp strip (39*4 rounded + z at 156)

__device__ __forceinline__ float sgn035(float t) {
    return __uint_as_float((__float_as_uint(t) & 0x80000000u) | 0x3EB33333u);
}

__global__ __launch_bounds__(NTHR, 4)
void tse_kernel(const float* __restrict__ x,
                const float* __restrict__ w_att,
                const float* __restrict__ b_att,
                float* __restrict__ out)
{
    // per-warp strip: [0..155] = e[n][h], [156..159] = Z[h]
    __shared__ __align__(16) float se[(NTHR / 32) * SEPITCH];

    const int warp  = threadIdx.x >> 5;
    const int lane  = threadIdx.x & 31;
    const int slice = blockIdx.x * (NTHR / 32) + warp;
    const float* __restrict__ xb = x + slice * (40 * DIM);
    const bool act = (lane < 25);
    const int g = lane >> 3;                 // this lane's head group
    float* __restrict__ sw = se + warp * SEPITCH;

    // ---- register params: r1 = t*wa, b1 = t*ba, k35 = copysign(0.35, t) ----
    float4 r1[NH], b1[NH], k35;
    #pragma unroll
    for (int h = 0; h < NH; h++) {
        r1[h] = make_float4(0.f, 0.f, 0.f, 0.f);
        b1[h] = make_float4(0.f, 0.f, 0.f, 0.f);
    }
    k35 = make_float4(0.f, 0.f, 0.f, 0.f);
    if (act) {
        const float4 t4 = reinterpret_cast<const float4*>(xb)[lane];
        k35.x = sgn035(t4.x); k35.y = sgn035(t4.y);
        k35.z = sgn035(t4.z); k35.w = sgn035(t4.w);
        #pragma unroll
        for (int h = 0; h < NH; h++) {
            const float4 wv = *reinterpret_cast<const float4*>(w_att + h * DIM + 4 * lane);
            const float4 bv = *reinterpret_cast<const float4*>(b_att + h * DIM + 4 * lane);
            r1[h].x = t4.x * wv.x; r1[h].y = t4.y * wv.y;
            r1[h].z = t4.z * wv.z; r1[h].w = t4.w * wv.w;
            b1[h].x = t4.x * bv.x; b1[h].y = t4.y * bv.y;
            b1[h].z = t4.z * bv.z; b1[h].w = t4.w * bv.w;
        }
    }

    const float* __restrict__ rp = xb + DIM + 4 * lane;

    // ---- phase 1: all 39 rows, independent per-row work, e -> smem strip ----
    float zacc = 0.f;
    #pragma unroll 3
    for (int n = 0; n < NW; n++) {
        float4 w4 = make_float4(0.f, 0.f, 0.f, 0.f);
        if (act) w4 = *reinterpret_cast<const float4*>(rp + n * DIM);

        float a[NH];
        #pragma unroll
        for (int h = 0; h < NH; h++) {
            float y, sa, sb;
            y  = fmaf(w4.x, r1[h].x, b1[h].x);
            sa = y * 0.65f;
            sb = k35.x * fabsf(y);
            y  = fmaf(w4.y, r1[h].y, b1[h].y);
            sa = fmaf(y, 0.65f, sa);
            sb = fmaf(k35.y, fabsf(y), sb);
            y  = fmaf(w4.z, r1[h].z, b1[h].z);
            sa = fmaf(y, 0.65f, sa);
            sb = fmaf(k35.z, fabsf(y), sb);
            y  = fmaf(w4.w, r1[h].w, b1[h].w);
            sa = fmaf(y, 0.65f, sa);
            sb = fmaf(k35.w, fabsf(y), sb);
            a[h] = sa + sb;
        }

        // packed butterfly: head-g total lands on all 8 lanes of group g
        const bool lo = (lane < 16);
        float xv = __shfl_xor_sync(0xffffffffu, lo ? a[2] : a[0], 16);
        float yv = __shfl_xor_sync(0xffffffffu, lo ? a[3] : a[1], 16);
        float u0 = (lo ? a[0] : a[2]) + xv;
        float u1 = (lo ? a[1] : a[3]) + yv;
        const bool b3 = (lane & 8) != 0;
        float zv = __shfl_xor_sync(0xffffffffu, b3 ? u0 : u1, 8);
        float t  = (b3 ? u1 : u0) + zv;
        t += __shfl_xor_sync(0xffffffffu, t, 4);
        t += __shfl_xor_sync(0xffffffffu, t, 2);
        t += __shfl_xor_sync(0xffffffffu, t, 1);

        const float e = __expf(t);
        zacc += e;
        if ((lane & 7) == 0) sw[n * NH + g] = e;
    }
    if ((lane & 7) == 0) sw[156 + g] = zacc;
    __syncwarp();

    // ---- phase 3: re-stream rows (L2-hot), absolute-head accumulators ----
    float4 acc[NH];
    #pragma unroll
    for (int h = 0; h < NH; h++) acc[h] = make_float4(0.f, 0.f, 0.f, 0.f);

    #pragma unroll 4
    for (int n = 0; n < NW; n++) {
        float4 w4 = make_float4(0.f, 0.f, 0.f, 0.f);
        if (act) w4 = *reinterpret_cast<const float4*>(rp + n * DIM);
        const float4 e4 = *reinterpret_cast<const float4*>(sw + n * NH);  // broadcast
        acc[0].x = fmaf(e4.x, w4.x, acc[0].x); acc[0].y = fmaf(e4.x, w4.y, acc[0].y);
        acc[0].z = fmaf(e4.x, w4.z, acc[0].z); acc[0].w = fmaf(e4.x, w4.w, acc[0].w);
        acc[1].x = fmaf(e4.y, w4.x, acc[1].x); acc[1].y = fmaf(e4.y, w4.y, acc[1].y);
        acc[1].z = fmaf(e4.y, w4.z, acc[1].z); acc[1].w = fmaf(e4.y, w4.w, acc[1].w);
        acc[2].x = fmaf(e4.z, w4.x, acc[2].x); acc[2].y = fmaf(e4.z, w4.y, acc[2].y);
        acc[2].z = fmaf(e4.z, w4.z, acc[2].z); acc[2].w = fmaf(e4.z, w4.w, acc[2].w);
        acc[3].x = fmaf(e4.w, w4.x, acc[3].x); acc[3].y = fmaf(e4.w, w4.y, acc[3].y);
        acc[3].z = fmaf(e4.w, w4.z, acc[3].z); acc[3].w = fmaf(e4.w, w4.w, acc[3].w);
    }

    // ---- normalize + store (warp-local, no block barrier anywhere) ----
    if (act) {
        float* ob = out + slice * (NH * DIM);
        const float4 z4 = *reinterpret_cast<const float4*>(sw + 156);
        const float inv[NH] = { 1.f / z4.x, 1.f / z4.y, 1.f / z4.z, 1.f / z4.w };
        #pragma unroll
        for (int h = 0; h < NH; h++) {
            float4 v = acc[h];
            v.x *= inv[h]; v.y *= inv[h]; v.z *= inv[h]; v.w *= inv[h];
            *reinterpret_cast<float4*>(ob + h * DIM + 4 * lane) = v;
        }
    }
}

extern "C" void kernel_launch(void* const* d_in, const int* in_sizes, int n_in,
                              void* d_out, int out_size)
{
    const float* x     = (const float*)d_in[0];
    const float* w_att = (const float*)d_in[1];
    const float* b_att = (const float*)d_in[2];
    float* out = (float*)d_out;
    tse_kernel<<<NBLK, NTHR>>>(x, w_att, b_att, out);
}

// round 13
// speedup vs baseline: 1.2464x; 1.2464x over previous
#include <cuda_runtime.h>

#define DIM   100
#define NW    39
#define NH    4
#define NBLK  4800          // one slice per block
#define NTHR  128
#define NWARP 4
#define NQ    25            // float4 chunks per 100-float row
#define RPW   10            // rows per warp (ceil(39/4))

__device__ __forceinline__ float sgn035(float t) {
    return __uint_as_float((__float_as_uint(t) & 0x80000000u) | 0x3EB33333u);
}

__global__ __launch_bounds__(NTHR, 8)
void tse_kernel(const float* __restrict__ x,
                const float* __restrict__ w_att,
                const float* __restrict__ b_att,
                float* __restrict__ out)
{
    __shared__ __align__(16) float se[40 * NH];             // exp(scores) [n][h] (warp-local use)
    __shared__ float sz[NWARP * NH];                        // per-warp Z partials
    __shared__ __align__(16) float4 sp4[NWARP * NH * NQ];   // partials (6.4 KB)

    const int tid  = threadIdx.x;
    const int warp = tid >> 5;
    const int lane = tid & 31;
    const int bid  = blockIdx.x;
    const float* __restrict__ xb = x + bid * (40 * DIM);
    const bool act = (lane < NQ);

    // ---- register params: r1 = t*wa, b1 = t*ba, k35 = copysign(0.35, t) ----
    float4 r1[NH], b1[NH], k35;
    #pragma unroll
    for (int h = 0; h < NH; h++) {
        r1[h] = make_float4(0.f, 0.f, 0.f, 0.f);
        b1[h] = make_float4(0.f, 0.f, 0.f, 0.f);
    }
    k35 = make_float4(0.f, 0.f, 0.f, 0.f);
    if (act) {
        const float4 t4 = reinterpret_cast<const float4*>(xb)[lane];
        k35.x = sgn035(t4.x); k35.y = sgn035(t4.y);
        k35.z = sgn035(t4.z); k35.w = sgn035(t4.w);
        #pragma unroll
        for (int h = 0; h < NH; h++) {
            const float4 wv = *reinterpret_cast<const float4*>(w_att + h * DIM + 4 * lane);
            const float4 bv = *reinterpret_cast<const float4*>(b_att + h * DIM + 4 * lane);
            r1[h].x = t4.x * wv.x; r1[h].y = t4.y * wv.y;
            r1[h].z = t4.z * wv.z; r1[h].w = t4.w * wv.w;
            b1[h].x = t4.x * bv.x; b1[h].y = t4.y * bv.y;
            b1[h].z = t4.z * bv.z; b1[h].w = t4.w * bv.w;
        }
    }

    const float* __restrict__ rp = xb + DIM + 4 * lane;

    // ---- phase 1: double-buffered row loads, 3-FFMA/element score math ----
    float zacc = 0.f;
    float4 w_cur = make_float4(0.f, 0.f, 0.f, 0.f);
    if (act) w_cur = *reinterpret_cast<const float4*>(rp + warp * DIM);

    #pragma unroll
    for (int k = 0; k < RPW; k++) {
        const int n = warp + k * NWARP;
        float4 w_nxt = make_float4(0.f, 0.f, 0.f, 0.f);
        if (k + 1 < RPW) {
            const int n2 = warp + (k + 1) * NWARP;
            if (act && n2 < NW)
                w_nxt = *reinterpret_cast<const float4*>(rp + n2 * DIM);
        }

        float a[NH];
        #pragma unroll
        for (int h = 0; h < NH; h++) {
            float y, sa, sb;
            y  = fmaf(w_cur.x, r1[h].x, b1[h].x);
            sa = y * 0.65f;
            sb = k35.x * fabsf(y);
            y  = fmaf(w_cur.y, r1[h].y, b1[h].y);
            sa = fmaf(y, 0.65f, sa);
            sb = fmaf(k35.y, fabsf(y), sb);
            y  = fmaf(w_cur.z, r1[h].z, b1[h].z);
            sa = fmaf(y, 0.65f, sa);
            sb = fmaf(k35.z, fabsf(y), sb);
            y  = fmaf(w_cur.w, r1[h].w, b1[h].w);
            sa = fmaf(y, 0.65f, sa);
            sb = fmaf(k35.w, fabsf(y), sb);
            a[h] = sa + sb;
        }

        // packed butterfly: head-g total lands on ALL 8 lanes of group g
        const bool lo = (lane < 16);
        float xv = __shfl_xor_sync(0xffffffffu, lo ? a[2] : a[0], 16);
        float yv = __shfl_xor_sync(0xffffffffu, lo ? a[3] : a[1], 16);
        float u0 = (lo ? a[0] : a[2]) + xv;
        float u1 = (lo ? a[1] : a[3]) + yv;
        const bool b3 = (lane & 8) != 0;
        float zv = __shfl_xor_sync(0xffffffffu, b3 ? u0 : u1, 8);
        float t  = (b3 ? u1 : u0) + zv;
        t += __shfl_xor_sync(0xffffffffu, t, 4);
        t += __shfl_xor_sync(0xffffffffu, t, 2);
        t += __shfl_xor_sync(0xffffffffu, t, 1);

        const float e = __expf(t);
        if (n < NW) {
            if ((lane & 7) == 0) se[n * NH + (lane >> 3)] = e;
            zacc += e;                  // this lane's group-head Z partial
        }

        w_cur = w_nxt;
    }
    __syncwarp();   // phase 3 reads only this warp's se rows (written by this warp)

    // ---- phase 3: rows re-loaded (L1/L2-hot) with double-buffer ----
    float4 acc[NH];
    #pragma unroll
    for (int h = 0; h < NH; h++) acc[h] = make_float4(0.f, 0.f, 0.f, 0.f);

    w_cur = make_float4(0.f, 0.f, 0.f, 0.f);
    if (act) w_cur = *reinterpret_cast<const float4*>(rp + warp * DIM);

    #pragma unroll
    for (int k = 0; k < RPW; k++) {
        const int n = warp + k * NWARP;
        float4 w_nxt = make_float4(0.f, 0.f, 0.f, 0.f);
        if (k + 1 < RPW) {
            const int n2 = warp + (k + 1) * NWARP;
            if (act && n2 < NW)
                w_nxt = *reinterpret_cast<const float4*>(rp + n2 * DIM);
        }

        float4 e4 = make_float4(0.f, 0.f, 0.f, 0.f);
        if (n < NW) e4 = *reinterpret_cast<const float4*>(se + n * NH);  // warp-local broadcast
        acc[0].x = fmaf(e4.x, w_cur.x, acc[0].x); acc[0].y = fmaf(e4.x, w_cur.y, acc[0].y);
        acc[0].z = fmaf(e4.x, w_cur.z, acc[0].z); acc[0].w = fmaf(e4.x, w_cur.w, acc[0].w);
        acc[1].x = fmaf(e4.y, w_cur.x, acc[1].x); acc[1].y = fmaf(e4.y, w_cur.y, acc[1].y);
        acc[1].z = fmaf(e4.y, w_cur.z, acc[1].z); acc[1].w = fmaf(e4.y, w_cur.w, acc[1].w);
        acc[2].x = fmaf(e4.z, w_cur.x, acc[2].x); acc[2].y = fmaf(e4.z, w_cur.y, acc[2].y);
        acc[2].z = fmaf(e4.z, w_cur.z, acc[2].z); acc[2].w = fmaf(e4.z, w_cur.w, acc[2].w);
        acc[3].x = fmaf(e4.w, w_cur.x, acc[3].x); acc[3].y = fmaf(e4.w, w_cur.y, acc[3].y);
        acc[3].z = fmaf(e4.w, w_cur.z, acc[3].z); acc[3].w = fmaf(e4.w, w_cur.w, acc[3].w);

        w_cur = w_nxt;
    }

    // ---- per-warp partials + Z partials ----
    if (act) {
        #pragma unroll
        for (int h = 0; h < NH; h++)
            sp4[(warp * NH + h) * NQ + lane] = acc[h];
    }
    if ((lane & 7) == 0) sz[warp * NH + (lane >> 3)] = zacc;
    __syncthreads();   // single 128-thread barrier

    // ---- cross-warp reduce (4 partials) + normalize + float4 store ----
    if (tid < NH * NQ) {
        const int h = tid / NQ;
        const int i = tid - h * NQ;
        float4 v = sp4[h * NQ + i];
        float  Z = sz[h];
        #pragma unroll
        for (int w = 1; w < NWARP; w++) {
            const float4 p = sp4[(w * NH + h) * NQ + i];
            v.x += p.x; v.y += p.y; v.z += p.z; v.w += p.w;
            Z += sz[w * NH + h];
        }
        const float si = 1.f / Z;
        v.x *= si; v.y *= si; v.z *= si; v.w *= si;
        reinterpret_cast<float4*>(out + bid * (NH * DIM))[tid] = v;
    }
}

extern "C" void kernel_launch(void* const* d_in, const int* in_sizes, int n_in,
                              void* d_out, int out_size)
{
    const float* x     = (const float*)d_in[0];
    const float* w_att = (const float*)d_in[1];
    const float* b_att = (const float*)d_in[2];
    float* out = (float*)d_out;
    tse_kernel<<<NBLK, NTHR>>>(x, w_att, b_att, out);
}